// round 6
// baseline (speedup 1.0000x reference)
#include <cuda_runtime.h>

// MovingNCA, plane-reduced formulation:
//  state(96ch) replaced by 9 planes P_ij = <state, comms_w[i,j,:]>.
//  comms a = b_c + sum_ij P_ij(n+i,m+j); percep b = 3x3 img gather at perc pos.
//  s_c = sigmoid(a*u_c + b*v_c + ob_c); planes += W^T s; class ch -> scratch.
// R6: occupancy via grid size. 1 cell/thread (instr/cell only ~+10% vs 2),
//     1024 blocks x 256 thr = 8128 warps chip-wide, __launch_bounds__(256,6)
//     (42 regs, 48 warps/SM resident).

#define N_NEO 510
#define G     512
#define G2    (G * G)
#define NCELLS (N_NEO * N_NEO)
#define NCA_THRESH 0.0007f
#define NLOG2E (-1.4426950408889634f)

__device__ float   g_h[2][9][G2];       // ping-pong comms planes
__device__ float   g_cls[32][NCELLS];   // transposed class accumulators
__device__ ushort2 g_perc[NCELLS];      // perception positions

__global__ void nca_init() {
    long stride = (long)gridDim.x * blockDim.x;
    long tid = (long)blockIdx.x * blockDim.x + threadIdx.x;
    float* h = &g_h[0][0][0];
    for (long i = tid; i < 2L * 9 * G2; i += stride) h[i] = 0.0f;
    float* c = &g_cls[0][0];
    for (long i = tid; i < 32L * NCELLS; i += stride) c[i] = 0.0f;
    for (long i = tid; i < NCELLS; i += stride)
        g_perc[i] = make_ushort2((unsigned short)(i / N_NEO),
                                 (unsigned short)(i % N_NEO));
}

__global__ void nca_final(float* __restrict__ out) {
    int cell = blockIdx.x * 256 + threadIdx.x;
    if (cell >= NCELLS) return;
    float* op = out + (size_t)cell * 32;
#pragma unroll
    for (int k = 0; k < 32; k += 4) {
        float4 v;
        v.x = g_cls[k + 0][cell];
        v.y = g_cls[k + 1][cell];
        v.z = g_cls[k + 2][cell];
        v.w = g_cls[k + 3][cell];
        *reinterpret_cast<float4*>(op + k) = v;
    }
}

// weights prescaled by -log2(e): computes sigmoid(z) from x = -log2(e)*z
__device__ __forceinline__ float sigmoid_pre(float x) {
    float e;
    asm("ex2.approx.f32 %0, %1;" : "=f"(e) : "f"(x));
    float r;
    asm("rcp.approx.f32 %0, %1;" : "=f"(r) : "f"(1.0f + e));
    return r;
}

__global__ __launch_bounds__(256, 6) void nca_step(
    const float* __restrict__ img,
    const float* __restrict__ comms_w,
    const float* __restrict__ comms_b,
    const float* __restrict__ perc_w,
    const float* __restrict__ perc_b,
    const float* __restrict__ out_w,
    const float* __restrict__ out_b,
    int parity)
{
    __shared__ __align__(16) float scw[9 * 96];   // comms_w [ij][c]
    __shared__ __align__(16) float su[100], sv[100], sob[100];  // prescaled
    __shared__ float spw[9];
    __shared__ float sbias[2];                    // [0]=perc_b [1]=comms_b

    int t = threadIdx.y * 32 + threadIdx.x;
    for (int i = t; i < 864; i += 256) scw[i] = comms_w[i];
    if (t < 98) {
        su[t]  = NLOG2E * out_w[t];
        sv[t]  = NLOG2E * out_w[98 + t];
        sob[t] = NLOG2E * out_b[t];
    }
    else if (t < 107) spw[t - 98] = perc_w[t - 98];
    else if (t == 107) sbias[0] = perc_b[0];
    else if (t == 108) sbias[1] = comms_b[0];
    __syncthreads();

    int n = blockIdx.y * 8 + threadIdx.y;
    int mm = blockIdx.x * 32 + threadIdx.x;
    bool valid = (n < N_NEO) && (mm < N_NEO);
    int nc = n  < N_NEO ? n  : (N_NEO - 1);
    int mc = mm < N_NEO ? mm : (N_NEO - 1);
    int cell = nc * N_NEO + mc;

    const float* __restrict__ hOld = &g_h[parity][0][0];
    float* __restrict__ hNew = &g_h[parity ^ 1][0][0];

    // comms gather over 9 planes
    float a = sbias[1];
#pragma unroll
    for (int q = 0; q < 9; q++) {
        int i = q / 3, j = q % 3;
        a += hOld[q * G2 + (nc + i) * G + (mc + j)];
    }

    // perception: 3x3 img patch at perc position
    ushort2 p = g_perc[cell];
    float b = sbias[0];
#pragma unroll
    for (int q = 0; q < 9; q++) {
        int i = q / 3, j = q % 3;
        b = fmaf(img[(p.x + i) * G + (p.y + j)], spw[q], b);
    }

    float acc[9];
#pragma unroll
    for (int q = 0; q < 9; q++) acc[q] = 0.0f;

    // ---- hidden channels 0..63 ----
#pragma unroll 2
    for (int c4 = 0; c4 < 64; c4 += 4) {
        float4 u4 = *reinterpret_cast<const float4*>(&su[c4]);
        float4 v4 = *reinterpret_cast<const float4*>(&sv[c4]);
        float4 o4 = *reinterpret_cast<const float4*>(&sob[c4]);
        float s0 = sigmoid_pre(fmaf(a, u4.x, fmaf(b, v4.x, o4.x)));
        float s1 = sigmoid_pre(fmaf(a, u4.y, fmaf(b, v4.y, o4.y)));
        float s2 = sigmoid_pre(fmaf(a, u4.z, fmaf(b, v4.z, o4.z)));
        float s3 = sigmoid_pre(fmaf(a, u4.w, fmaf(b, v4.w, o4.w)));
#pragma unroll
        for (int q = 0; q < 9; q++) {
            float4 w4 = *reinterpret_cast<const float4*>(&scw[q * 96 + c4]);
            acc[q] = fmaf(w4.x, s0, fmaf(w4.y, s1,
                     fmaf(w4.z, s2, fmaf(w4.w, s3, acc[q]))));
        }
    }

    // ---- class channels 64..95 (also RMW into transposed scratch) ----
#pragma unroll 1
    for (int c4 = 64; c4 < 96; c4 += 4) {
        float4 u4 = *reinterpret_cast<const float4*>(&su[c4]);
        float4 v4 = *reinterpret_cast<const float4*>(&sv[c4]);
        float4 o4 = *reinterpret_cast<const float4*>(&sob[c4]);
        float s0 = sigmoid_pre(fmaf(a, u4.x, fmaf(b, v4.x, o4.x)));
        float s1 = sigmoid_pre(fmaf(a, u4.y, fmaf(b, v4.y, o4.y)));
        float s2 = sigmoid_pre(fmaf(a, u4.z, fmaf(b, v4.z, o4.z)));
        float s3 = sigmoid_pre(fmaf(a, u4.w, fmaf(b, v4.w, o4.w)));
        if (valid) {
            g_cls[c4 - 64 + 0][cell] += s0;   // coalesced across lanes
            g_cls[c4 - 64 + 1][cell] += s1;
            g_cls[c4 - 64 + 2][cell] += s2;
            g_cls[c4 - 64 + 3][cell] += s3;
        }
#pragma unroll
        for (int q = 0; q < 9; q++) {
            float4 w4 = *reinterpret_cast<const float4*>(&scw[q * 96 + c4]);
            acc[q] = fmaf(w4.x, s0, fmaf(w4.y, s1,
                     fmaf(w4.z, s2, fmaf(w4.w, s3, acc[q]))));
        }
    }

    // ---- plane writes + action/perc update ----
    if (valid) {
        int hc = (n + 1) * G + (mm + 1);
#pragma unroll
        for (int q = 0; q < 9; q++)
            hNew[q * G2 + hc] = hOld[q * G2 + hc] + acc[q];

        float s0 = sigmoid_pre(fmaf(a, su[96], fmaf(b, sv[96], sob[96])));
        float s1 = sigmoid_pre(fmaf(a, su[97], fmaf(b, sv[97], sob[97])));
        int dx = (s0 > NCA_THRESH) ? 1 : ((s0 < -NCA_THRESH) ? -1 : 0);
        int dy = (s1 > NCA_THRESH) ? 1 : ((s1 < -NCA_THRESH) ? -1 : 0);
        int px = min(max((int)p.x + dx, 0), N_NEO - 1);
        int py = min(max((int)p.y + dy, 0), N_NEO - 1);
        g_perc[cell] = make_ushort2((unsigned short)px, (unsigned short)py);
    }
}

extern "C" void kernel_launch(void* const* d_in, const int* in_sizes, int n_in,
                              void* d_out, int out_size) {
    const float* img     = (const float*)d_in[0];
    const float* comms_w = (const float*)d_in[1];
    const float* comms_b = (const float*)d_in[2];
    const float* perc_w  = (const float*)d_in[3];
    const float* perc_b  = (const float*)d_in[4];
    const float* out_w   = (const float*)d_in[5];
    const float* out_b   = (const float*)d_in[6];
    float* out = (float*)d_out;

    nca_init<<<1024, 256>>>();

    dim3 bs(32, 8);
    dim3 gs((N_NEO + 31) / 32, (N_NEO + 7) / 8);   // 16 x 64 = 1024 blocks
    for (int t = 0; t < 50; t++)
        nca_step<<<gs, bs>>>(img, comms_w, comms_b, perc_w, perc_b,
                             out_w, out_b, t & 1);

    nca_final<<<(NCELLS + 255) / 256, 256>>>(out);
}

// round 7
// speedup vs baseline: 1.0037x; 1.0037x over previous
#include <cuda_runtime.h>

// MovingNCA, plane-reduced formulation:
//  state(96ch) replaced by 9 planes P_ij = <state, comms_w[i,j,:]>.
//  comms a = b_c + sum_ij P_ij(n+i,m+j); percep b = 3x3 img gather at perc pos.
//  s_c = sigmoid(a*u_c + b*v_c + ob_c); planes += W^T s; class ch -> scratch.
// R7: single-wave max residency. 1 cell/thread, 128-thr blocks, 2048 blocks,
//     __launch_bounds__(128,14) -> 36 regs, 56 warps/SM, all blocks resident
//     in one wave (148*14 = 2072 >= 2048, no tail).

#define N_NEO 510
#define G     512
#define G2    (G * G)
#define NCELLS (N_NEO * N_NEO)
#define NCA_THRESH 0.0007f
#define NLOG2E (-1.4426950408889634f)

__device__ float   g_h[2][9][G2];       // ping-pong comms planes
__device__ float   g_cls[32][NCELLS];   // transposed class accumulators
__device__ ushort2 g_perc[NCELLS];      // perception positions

__global__ void nca_init() {
    long stride = (long)gridDim.x * blockDim.x;
    long tid = (long)blockIdx.x * blockDim.x + threadIdx.x;
    float* h = &g_h[0][0][0];
    for (long i = tid; i < 2L * 9 * G2; i += stride) h[i] = 0.0f;
    float* c = &g_cls[0][0];
    for (long i = tid; i < 32L * NCELLS; i += stride) c[i] = 0.0f;
    for (long i = tid; i < NCELLS; i += stride)
        g_perc[i] = make_ushort2((unsigned short)(i / N_NEO),
                                 (unsigned short)(i % N_NEO));
}

__global__ void nca_final(float* __restrict__ out) {
    int cell = blockIdx.x * 256 + threadIdx.x;
    if (cell >= NCELLS) return;
    float* op = out + (size_t)cell * 32;
#pragma unroll
    for (int k = 0; k < 32; k += 4) {
        float4 v;
        v.x = g_cls[k + 0][cell];
        v.y = g_cls[k + 1][cell];
        v.z = g_cls[k + 2][cell];
        v.w = g_cls[k + 3][cell];
        *reinterpret_cast<float4*>(op + k) = v;
    }
}

// weights prescaled by -log2(e): computes sigmoid(z) from x = -log2(e)*z
__device__ __forceinline__ float sigmoid_pre(float x) {
    float e;
    asm("ex2.approx.f32 %0, %1;" : "=f"(e) : "f"(x));
    float r;
    asm("rcp.approx.f32 %0, %1;" : "=f"(r) : "f"(1.0f + e));
    return r;
}

__global__ __launch_bounds__(128, 14) void nca_step(
    const float* __restrict__ img,
    const float* __restrict__ comms_w,
    const float* __restrict__ comms_b,
    const float* __restrict__ perc_w,
    const float* __restrict__ perc_b,
    const float* __restrict__ out_w,
    const float* __restrict__ out_b,
    int parity)
{
    __shared__ __align__(16) float scw[9 * 96];   // comms_w [ij][c]
    __shared__ __align__(16) float su[100], sv[100], sob[100];  // prescaled
    __shared__ float spw[9];
    __shared__ float sbias[2];                    // [0]=perc_b [1]=comms_b

    int t = threadIdx.y * 32 + threadIdx.x;
    for (int i = t; i < 864; i += 128) scw[i] = comms_w[i];
    if (t < 98) {
        su[t]  = NLOG2E * out_w[t];
        sv[t]  = NLOG2E * out_w[98 + t];
        sob[t] = NLOG2E * out_b[t];
    }
    else if (t < 107) spw[t - 98] = perc_w[t - 98];
    else if (t == 107) sbias[0] = perc_b[0];
    else if (t == 108) sbias[1] = comms_b[0];
    __syncthreads();

    int n  = blockIdx.y * 4 + threadIdx.y;
    int mm = blockIdx.x * 32 + threadIdx.x;
    bool valid = (n < N_NEO) && (mm < N_NEO);
    int nc = n  < N_NEO ? n  : (N_NEO - 1);
    int mc = mm < N_NEO ? mm : (N_NEO - 1);
    int cell = nc * N_NEO + mc;

    const float* __restrict__ hOld = &g_h[parity][0][0];
    float* __restrict__ hNew = &g_h[parity ^ 1][0][0];

    // comms gather over 9 planes
    float a = sbias[1];
#pragma unroll
    for (int q = 0; q < 9; q++) {
        int i = q / 3, j = q % 3;
        a += hOld[q * G2 + (nc + i) * G + (mc + j)];
    }

    // perception: 3x3 img patch at perc position
    ushort2 p = g_perc[cell];
    float b = sbias[0];
#pragma unroll
    for (int q = 0; q < 9; q++) {
        int i = q / 3, j = q % 3;
        b = fmaf(img[(p.x + i) * G + (p.y + j)], spw[q], b);
    }

    float acc[9];
#pragma unroll
    for (int q = 0; q < 9; q++) acc[q] = 0.0f;

    // ---- hidden channels 0..63 ----
#pragma unroll 2
    for (int c4 = 0; c4 < 64; c4 += 4) {
        float4 u4 = *reinterpret_cast<const float4*>(&su[c4]);
        float4 v4 = *reinterpret_cast<const float4*>(&sv[c4]);
        float4 o4 = *reinterpret_cast<const float4*>(&sob[c4]);
        float s0 = sigmoid_pre(fmaf(a, u4.x, fmaf(b, v4.x, o4.x)));
        float s1 = sigmoid_pre(fmaf(a, u4.y, fmaf(b, v4.y, o4.y)));
        float s2 = sigmoid_pre(fmaf(a, u4.z, fmaf(b, v4.z, o4.z)));
        float s3 = sigmoid_pre(fmaf(a, u4.w, fmaf(b, v4.w, o4.w)));
#pragma unroll
        for (int q = 0; q < 9; q++) {
            float4 w4 = *reinterpret_cast<const float4*>(&scw[q * 96 + c4]);
            acc[q] = fmaf(w4.x, s0, fmaf(w4.y, s1,
                     fmaf(w4.z, s2, fmaf(w4.w, s3, acc[q]))));
        }
    }

    // ---- class channels 64..95 (also RMW into transposed scratch) ----
#pragma unroll 1
    for (int c4 = 64; c4 < 96; c4 += 4) {
        float4 u4 = *reinterpret_cast<const float4*>(&su[c4]);
        float4 v4 = *reinterpret_cast<const float4*>(&sv[c4]);
        float4 o4 = *reinterpret_cast<const float4*>(&sob[c4]);
        float s0 = sigmoid_pre(fmaf(a, u4.x, fmaf(b, v4.x, o4.x)));
        float s1 = sigmoid_pre(fmaf(a, u4.y, fmaf(b, v4.y, o4.y)));
        float s2 = sigmoid_pre(fmaf(a, u4.z, fmaf(b, v4.z, o4.z)));
        float s3 = sigmoid_pre(fmaf(a, u4.w, fmaf(b, v4.w, o4.w)));
        if (valid) {
            g_cls[c4 - 64 + 0][cell] += s0;   // coalesced across lanes
            g_cls[c4 - 64 + 1][cell] += s1;
            g_cls[c4 - 64 + 2][cell] += s2;
            g_cls[c4 - 64 + 3][cell] += s3;
        }
#pragma unroll
        for (int q = 0; q < 9; q++) {
            float4 w4 = *reinterpret_cast<const float4*>(&scw[q * 96 + c4]);
            acc[q] = fmaf(w4.x, s0, fmaf(w4.y, s1,
                     fmaf(w4.z, s2, fmaf(w4.w, s3, acc[q]))));
        }
    }

    // ---- plane writes + action/perc update ----
    if (valid) {
        int hc = (n + 1) * G + (mm + 1);
#pragma unroll
        for (int q = 0; q < 9; q++)
            hNew[q * G2 + hc] = hOld[q * G2 + hc] + acc[q];

        float s0 = sigmoid_pre(fmaf(a, su[96], fmaf(b, sv[96], sob[96])));
        float s1 = sigmoid_pre(fmaf(a, su[97], fmaf(b, sv[97], sob[97])));
        int dx = (s0 > NCA_THRESH) ? 1 : ((s0 < -NCA_THRESH) ? -1 : 0);
        int dy = (s1 > NCA_THRESH) ? 1 : ((s1 < -NCA_THRESH) ? -1 : 0);
        int px = min(max((int)p.x + dx, 0), N_NEO - 1);
        int py = min(max((int)p.y + dy, 0), N_NEO - 1);
        g_perc[cell] = make_ushort2((unsigned short)px, (unsigned short)py);
    }
}

extern "C" void kernel_launch(void* const* d_in, const int* in_sizes, int n_in,
                              void* d_out, int out_size) {
    const float* img     = (const float*)d_in[0];
    const float* comms_w = (const float*)d_in[1];
    const float* comms_b = (const float*)d_in[2];
    const float* perc_w  = (const float*)d_in[3];
    const float* perc_b  = (const float*)d_in[4];
    const float* out_w   = (const float*)d_in[5];
    const float* out_b   = (const float*)d_in[6];
    float* out = (float*)d_out;

    nca_init<<<1024, 256>>>();

    dim3 bs(32, 4);
    dim3 gs((N_NEO + 31) / 32, (N_NEO + 3) / 4);   // 16 x 128 = 2048 blocks
    for (int t = 0; t < 50; t++)
        nca_step<<<gs, bs>>>(img, comms_w, comms_b, perc_w, perc_b,
                             out_w, out_b, t & 1);

    nca_final<<<(NCELLS + 255) / 256, 256>>>(out);
}